// round 16
// baseline (speedup 1.0000x reference)
#include <cuda_runtime.h>
#include <cuda_bf16.h>

// B = 8192 rows, T = 4096 features, G = 64 groups.
// Group sizes cycle (32, 64, 96, 64) x 16; all boundaries are multiples of 32,
// so each aligned 32-elem chunk belongs to exactly one group (128 chunks/row).
// Output: d_out[0..B) = Z (fp32), d_out[B..B+B*64) = a (fp32 row-major [B,64]).
//
// R16 = R6 (best measured, re-confirmed 25.09us / DRAM 73.3%) with exactly ONE
// change: __ldcg on the four streaming loads (LDG.128.CG, L1-bypass). H is
// read-once; default .ca wastes L1 fill work in the same L1tex unit that
// serializes load wavefronts. Same regs/occupancy/schedule as R6.

#define T_DIM    4096
#define G_DIM    64
#define NTHREADS 256

__global__ __launch_bounds__(NTHREADS, 8)
void agp_kernel(const float* __restrict__ H,
                const float* __restrict__ score_w,
                const float* __restrict__ score_b,
                float* __restrict__ out, int B)
{
    const int b   = blockIdx.x;
    const int tid = threadIdx.x;

    __shared__ float chunk_sum[T_DIM / 32];   // 128 chunk sums

    const float4* row4 = reinterpret_cast<const float4*>(H + (size_t)b * T_DIM);

    // --- Phase 1: 4 coalesced LDG.128.CG per thread, butterfly to chunks ---
    #pragma unroll
    for (int k = 0; k < 4; ++k) {
        float4 v = __ldcg(row4 + tid + NTHREADS * k);
        float s = (v.x + v.y) + (v.z + v.w);
        // aligned 8-lane butterfly -> one 32-elem chunk sum
        s += __shfl_xor_sync(0xffffffffu, s, 1);
        s += __shfl_xor_sync(0xffffffffu, s, 2);
        s += __shfl_xor_sync(0xffffffffu, s, 4);
        if ((tid & 7) == 0)
            chunk_sum[(tid >> 3) + 32 * k] = s;
    }
    __syncthreads();

    // --- Phase 2: warp 0 does groups -> softmax -> Z ---
    if (tid < 32) {
        const float w    = __ldg(score_w);
        const float bias = __ldg(score_b);

        // per-subgroup (g & 3): chunk start within 8-chunk cycle, count, 1/size
        const int   c_start[4] = {0, 1, 3, 6};
        const int   c_cnt[4]   = {1, 2, 3, 2};
        const float inv_sz[4]  = {1.0f/32.0f, 1.0f/64.0f, 1.0f/96.0f, 1.0f/64.0f};

        float Gm[2], sc[2];
        #pragma unroll
        for (int j = 0; j < 2; ++j) {
            int g    = tid + 32 * j;
            int sub  = g & 3;
            int base = (g >> 2) * 8 + c_start[sub];
            float s = 0.0f;
            #pragma unroll
            for (int c = 0; c < 3; ++c)
                if (c < c_cnt[sub]) s += chunk_sum[base + c];
            Gm[j] = s * inv_sz[sub];
            sc[j] = Gm[j] * w + bias;
        }

        // max tree (required before exp)
        float mx = fmaxf(sc[0], sc[1]);
        #pragma unroll
        for (int d = 16; d > 0; d >>= 1)
            mx = fmaxf(mx, __shfl_xor_sync(0xffffffffu, mx, d));

        float p0 = __expf(sc[0] - mx);
        float p1 = __expf(sc[1] - mx);

        // interleaved independent trees: ssum = sum(p), pz = sum(p*G)
        float ssum = p0 + p1;
        float pz   = p0 * Gm[0] + p1 * Gm[1];
        #pragma unroll
        for (int d = 16; d > 0; d >>= 1) {
            ssum += __shfl_xor_sync(0xffffffffu, ssum, d);
            pz   += __shfl_xor_sync(0xffffffffu, pz, d);
        }
        float inv = 1.0f / ssum;

        float* a_out = out + B + (size_t)b * G_DIM;
        a_out[tid]      = p0 * inv;
        a_out[tid + 32] = p1 * inv;
        if (tid == 0) out[b] = pz * inv;   // Z = sum(a*G) = pz / ssum
    }
}

extern "C" void kernel_launch(void* const* d_in, const int* in_sizes, int n_in,
                              void* d_out, int out_size)
{
    const float* H  = (const float*)d_in[0];   // [B, 4096]
    const float* sw = (const float*)d_in[1];   // [1,1]
    const float* sb = (const float*)d_in[2];   // [1]
    float* out = (float*)d_out;

    int B = in_sizes[0] / T_DIM;               // 8192
    agp_kernel<<<B, NTHREADS>>>(H, sw, sb, out, B);
}